// round 11
// baseline (speedup 1.0000x reference)
#include <cuda_runtime.h>
#include <cuda_bf16.h>
#include <cstdint>

// Problem constants
#define RANK 2
#define INPUT_SIZE 8
#define HIDDEN 1024
#define NMIX 4
#define ALPHA 0.1f
#define BASE_SCALE 500.0f
#define DDIM 12              // 2*RANK + INPUT_SIZE
#define BATCH 64
#define SEQ 512
#define SPAN_D 10            // RANK + INPUT_SIZE

// ---------------- scratch (device globals: allocation-free) ----------------
__device__ float2 g_n2[HIDDEN];            // (n0, n1) per hidden unit
__device__ float2 g_mA[HIDDEN];            // alpha*s*(m0, m1)
__device__ float  g_IA[HIDDEN * 8];        // alpha*I  [h][8]
__device__ float  g_pinvT[HIDDEN * SPAN_D];// pinv transposed: [h][d]
__device__ float  g_hid[(size_t)BATCH * SEQ * HIDDEN]; // 128 MB hiddens

// HW tanh approximation: single MUFU op (sm_75+)
__device__ __forceinline__ float tanh_hw(float x) {
    float r;
    asm("tanh.approx.f32 %0, %1;" : "=f"(r) : "f"(x));
    return r;
}

// ============================ setup kernel ============================
__global__ void __launch_bounds__(1024) setup_kernel(
    const float* __restrict__ eps,     // (4,1024,12)
    const float* __restrict__ means,   // (4,12)
    const float* __restrict__ stril,   // (4,12,12)
    const float* __restrict__ mw)      // (4,)
{
    __shared__ float  sL[NMIX][DDIM][DDIM];
    __shared__ float  sM[NMIX][DDIM];
    __shared__ float  sw[NMIX];
    __shared__ float  sSpan[SPAN_D][HIDDEN]; // 40 KB: span transposed (contig per d)
    __shared__ float  sPart[100][8];   // Gram partials: pair x segment (fp32)
    __shared__ double sA[100];         // GJ workspace (fp64, tiny op count)
    __shared__ double sB[100];         // GJ inverse accumulator
    __shared__ float  sGf[100];        // Ginv in fp32

    const int tid = threadIdx.x;

    // L = tril(raw,-1) + (|diag-1e-12|+1e-12) * I
    if (tid < NMIX * DDIM * DDIM) {
        int r = (tid / DDIM) % DDIM;
        int c = tid % DDIM;
        float raw = stril[tid];
        float v;
        if (r > c)      v = raw;
        else if (r == c) v = fabsf(raw - 1e-12f) + 1e-12f;
        else            v = 0.f;
        sL[tid / (DDIM * DDIM)][r][c] = v;
    }
    if (tid < NMIX * DDIM) sM[tid / DDIM][tid % DDIM] = means[tid];
    if (tid == 0) {
        float t4[NMIX]; float s = 0.f;
        #pragma unroll
        for (int k = 0; k < NMIX; k++) { t4[k] = fmaxf(mw[k], 1e-6f); s += t4[k]; }
        #pragma unroll
        for (int k = 0; k < NMIX; k++) sw[k] = t4[k] / s;
    }
    __syncthreads();

    // mixed[h][e] = sum_k w_k * (means[k][e] + sum_{d<=e} eps[k,h,d]*L[k,e,d])
    const int h = tid;
    float mix[DDIM];
    #pragma unroll
    for (int e = 0; e < DDIM; e++) mix[e] = 0.f;

    #pragma unroll
    for (int k = 0; k < NMIX; k++) {
        float wk = sw[k];
        const float4* p = (const float4*)(eps + ((size_t)k * HIDDEN + h) * DDIM);
        float4 a = p[0], b = p[1], c = p[2];
        float ep[DDIM] = {a.x,a.y,a.z,a.w, b.x,b.y,b.z,b.w, c.x,c.y,c.z,c.w};
        #pragma unroll
        for (int e = 0; e < DDIM; e++) {
            float s = sM[k][e];
            #pragma unroll
            for (int d = 0; d <= e; d++) {   // L is lower-triangular
                s = fmaf(ep[d], sL[k][e][d], s);
            }
            mix[e] = fmaf(wk, s, mix[e]);
        }
    }

    // derive per-h constants
    const float AS = ALPHA * (BASE_SCALE / (float)HIDDEN);
    float span[SPAN_D];
    span[0] = mix[0]; span[1] = mix[1];
    #pragma unroll
    for (int d = 0; d < 8; d++) span[2 + d] = mix[4 + d];

    g_n2[h] = make_float2(mix[2], mix[3]);
    g_mA[h] = make_float2(AS * mix[0], AS * mix[1]);
    #pragma unroll
    for (int d = 0; d < 8; d++) g_IA[h * 8 + d] = ALPHA * mix[4 + d];
    #pragma unroll
    for (int d = 0; d < SPAN_D; d++) sSpan[d][h] = span[d];   // smem, transposed

    __syncthreads();

    // ---- Gram G = span^T span: fp32, contiguous float4 LDS (no global trip) ----
    if (tid < 800) {
        int p = tid >> 3;          // 0..99
        int seg = tid & 7;         // 0..7 -> 128 h each
        int a = p / 10, b = p % 10;
        const float4* pa = (const float4*)&sSpan[a][seg * 128];
        const float4* pb = (const float4*)&sSpan[b][seg * 128];
        float s0 = 0.f, s1 = 0.f, s2 = 0.f, s3 = 0.f;
        #pragma unroll 8
        for (int i = 0; i < 32; i++) {
            float4 va = pa[i], vb = pb[i];
            s0 = fmaf(va.x, vb.x, s0);
            s1 = fmaf(va.y, vb.y, s1);
            s2 = fmaf(va.z, vb.z, s2);
            s3 = fmaf(va.w, vb.w, s3);
        }
        sPart[p][seg] = (s0 + s1) + (s2 + s3);
    }
    __syncthreads();
    if (tid < 100) {
        double s = 0.0;
        #pragma unroll
        for (int seg = 0; seg < 8; seg++) s += (double)sPart[tid][seg];
        sA[tid] = s;
        sB[tid] = ((tid / 10) == (tid % 10)) ? 1.0 : 0.0;
    }

    // ---- parallel Gauss-Jordan inversion (SPD, no pivoting), 100 threads, fp64 ----
    const int gi = tid / 10, gj = tid % 10;
    #pragma unroll 1
    for (int k = 0; k < SPAN_D; k++) {
        __syncthreads();
        double piv = 0.0, akj = 0.0, bkj = 0.0, f = 0.0, aij = 0.0, bij = 0.0;
        if (tid < 100) {
            piv = sA[k * 10 + k];
            akj = sA[k * 10 + gj];
            bkj = sB[k * 10 + gj];
            f   = sA[gi * 10 + k];
            aij = sA[tid];
            bij = sB[tid];
        }
        __syncthreads();
        if (tid < 100) {
            double pinv = 1.0 / piv;
            if (gi == k) {
                sA[tid] = akj * pinv;
                sB[tid] = bkj * pinv;
            } else {
                double fp = f * pinv;
                sA[tid] = aij - fp * akj;
                sB[tid] = bij - fp * bkj;
            }
        }
    }
    __syncthreads();
    if (tid < 100) sGf[tid] = (float)sB[tid];
    __syncthreads();

    // pinv[d][h] = sum_j Ginv[d][j] * span[h][j]  (store transposed [h][d], fp32)
    #pragma unroll
    for (int d = 0; d < SPAN_D; d++) {
        float s = 0.f;
        #pragma unroll
        for (int j = 0; j < SPAN_D; j++) s = fmaf(sGf[d * 10 + j], span[j], s);
        g_pinvT[h * SPAN_D + d] = s;
    }
}

// ============================ RNN kernel ============================
// One CTA per batch. 256 threads, each owns 4 consecutive hidden units.
__global__ void __launch_bounds__(256, 1) rnn_kernel(const float* __restrict__ x)
{
    __shared__ float  sx[SEQ * INPUT_SIZE];   // 16 KB: x[b] staged
    __shared__ float4 sred[2][4];             // ping-pong: [w][0]=S0,[1]=S1 packed

    const int tid  = threadIdx.x;
    const int lane = tid & 31;
    const int wid  = tid >> 5;
    const int b    = blockIdx.x;

    // stage x[b] into smem (coalesced float4)
    #pragma unroll
    for (int i = 0; i < (SEQ * INPUT_SIZE / 4) / 256; i++)
        ((float4*)sx)[i * 256 + tid] =
            ((const float4*)(x + (size_t)b * SEQ * INPUT_SIZE))[i * 256 + tid];

    // per-thread constants for h = 4*tid .. 4*tid+3
    float n0[4], n1[4], m0[4], m1[4], IA[4][8];
    #pragma unroll
    for (int i = 0; i < 4; i++) {
        int hh = 4 * tid + i;
        float2 t = g_n2[hh]; n0[i] = t.x; n1[i] = t.y;
        t = g_mA[hh];        m0[i] = t.x; m1[i] = t.y;
        float4 a4 = ((const float4*)g_IA)[hh * 2 + 0];
        float4 b4 = ((const float4*)g_IA)[hh * 2 + 1];
        IA[i][0]=a4.x; IA[i][1]=a4.y; IA[i][2]=a4.z; IA[i][3]=a4.w;
        IA[i][4]=b4.x; IA[i][5]=b4.y; IA[i][6]=b4.z; IA[i][7]=b4.w;
    }

    float h[4] = {0.f, 0.f, 0.f, 0.f};
    float* hout = g_hid + ((size_t)b << 19) + 4 * tid;   // [b][t][h]
    const bool odd = (lane & 1);
    __syncthreads();

    int par = 0;
    #pragma unroll 1
    for (int t = 0; t < SEQ; t++) {
        // tanh via single MUFU op
        float th[4];
        #pragma unroll
        for (int i = 0; i < 4; i++) th[i] = tanh_hw(h[i]);

        // per-thread 4-way product tree
        float p0 = fmaf(th[0], n0[0], th[1] * n0[1]) + fmaf(th[2], n0[2], th[3] * n0[3]);
        float p1 = fmaf(th[0], n1[0], th[1] * n1[1]) + fmaf(th[2], n1[2], th[3] * n1[3]);

        // parity-split dual reduction: 5 shfls total (was 10).
        // pre-swap: even lanes accumulate p0-pair-sums, odd lanes p1-pair-sums
        float send = odd ? p0 : p1;
        float got  = __shfl_xor_sync(0xffffffffu, send, 1);
        float r    = (odd ? p1 : p0) + got;
        #pragma unroll
        for (int o = 2; o <= 16; o <<= 1)       // parity-preserving butterfly
            r += __shfl_xor_sync(0xffffffffu, r, o);
        // even lanes now hold warp-S0, odd lanes warp-S1
        if (lane < 2) ((float*)&sred[par][0])[wid * 2 + lane] = r;

        // x_t @ (alpha*I)^T  — independent of the reduction, overlaps shfl/bar
        float4 xa = ((const float4*)sx)[t * 2 + 0];
        float4 xb = ((const float4*)sx)[t * 2 + 1];
        float xi[4];
        #pragma unroll
        for (int i = 0; i < 4; i++) {
            xi[i] = xa.x*IA[i][0] + xa.y*IA[i][1] + xa.z*IA[i][2] + xa.w*IA[i][3]
                  + xb.x*IA[i][4] + xb.y*IA[i][5] + xb.z*IA[i][6] + xb.w*IA[i][7];
        }

        __syncthreads();
        // stage-2: 4 broadcast LDS.128 + depth-3 FADD tree
        float4 r0 = sred[par][0];
        float4 r1 = sred[par][1];
        float4 r2 = sred[par][2];
        float4 r3 = sred[par][3];
        float q0 = ((r0.x + r0.z) + (r1.x + r1.z)) + ((r2.x + r2.z) + (r3.x + r3.z));
        float q1 = ((r0.y + r0.w) + (r1.y + r1.w)) + ((r2.y + r2.w) + (r3.y + r3.w));

        // h_new = 0.9h + q0*mA0 + q1*mA1 + xi  (scales prefolded)
        #pragma unroll
        for (int i = 0; i < 4; i++)
            h[i] = fmaf(0.9f, h[i], fmaf(q0, m0[i], fmaf(q1, m1[i], xi[i])));

        *(float4*)(hout + ((size_t)t << 10)) = make_float4(h[0], h[1], h[2], h[3]);
        par ^= 1;
    }
}

// ============================ projection kernel ============================
// out[b,t,d] = sum_h pinv[d][h] * hid[b,t,h]; thread per (b,t).
__global__ void __launch_bounds__(256) proj_kernel(float* __restrict__ out)
{
    extern __shared__ float spv[];   // [1024][12] padded pinv rows, 48 KB
    const int tid = threadIdx.x;
    for (int i = tid; i < HIDDEN * 12; i += 256) {
        int hh = i / 12, d = i % 12;
        spv[i] = (d < SPAN_D) ? g_pinvT[hh * SPAN_D + d] : 0.f;
    }
    __syncthreads();

    const int bt = blockIdx.x * 256 + tid;          // 0..32767
    const float4* hp = (const float4*)(g_hid + (size_t)bt * HIDDEN);

    float acc[SPAN_D];
    #pragma unroll
    for (int d = 0; d < SPAN_D; d++) acc[d] = 0.f;

    #pragma unroll 4
    for (int j = 0; j < HIDDEN / 4; j++) {
        float4 hv = hp[j];
        const float* base = &spv[(j * 4) * 12];
        {
            const float4* pv = (const float4*)(base + 0);
            float4 a = pv[0], bq = pv[1], c = pv[2];
            acc[0] += hv.x*a.x;  acc[1] += hv.x*a.y;  acc[2] += hv.x*a.z;  acc[3] += hv.x*a.w;
            acc[4] += hv.x*bq.x; acc[5] += hv.x*bq.y; acc[6] += hv.x*bq.z; acc[7] += hv.x*bq.w;
            acc[8] += hv.x*c.x;  acc[9] += hv.x*c.y;
        }
        {
            const float4* pv = (const float4*)(base + 12);
            float4 a = pv[0], bq = pv[1], c = pv[2];
            acc[0] += hv.y*a.x;  acc[1] += hv.y*a.y;  acc[2] += hv.y*a.z;  acc[3] += hv.y*a.w;
            acc[4] += hv.y*bq.x; acc[5] += hv.y*bq.y; acc[6] += hv.y*bq.z; acc[7] += hv.y*bq.w;
            acc[8] += hv.y*c.x;  acc[9] += hv.y*c.y;
        }
        {
            const float4* pv = (const float4*)(base + 24);
            float4 a = pv[0], bq = pv[1], c = pv[2];
            acc[0] += hv.z*a.x;  acc[1] += hv.z*a.y;  acc[2] += hv.z*a.z;  acc[3] += hv.z*a.w;
            acc[4] += hv.z*bq.x; acc[5] += hv.z*bq.y; acc[6] += hv.z*bq.z; acc[7] += hv.z*bq.w;
            acc[8] += hv.z*c.x;  acc[9] += hv.z*c.y;
        }
        {
            const float4* pv = (const float4*)(base + 36);
            float4 a = pv[0], bq = pv[1], c = pv[2];
            acc[0] += hv.w*a.x;  acc[1] += hv.w*a.y;  acc[2] += hv.w*a.z;  acc[3] += hv.w*a.w;
            acc[4] += hv.w*bq.x; acc[5] += hv.w*bq.y; acc[6] += hv.w*bq.z; acc[7] += hv.w*bq.w;
            acc[8] += hv.w*c.x;  acc[9] += hv.w*c.y;
        }
    }

    float* op = out + (size_t)bt * SPAN_D;
    #pragma unroll
    for (int d = 0; d < SPAN_D; d++) op[d] = acc[d];
}

// ============================ launcher ============================
extern "C" void kernel_launch(void* const* d_in, const int* in_sizes, int n_in,
                              void* d_out, int out_size)
{
    const float* x     = (const float*)d_in[0];   // (64,512,8)
    const float* eps   = (const float*)d_in[1];   // (4,1024,12)
    const float* means = (const float*)d_in[2];   // (4,12)
    const float* stril = (const float*)d_in[3];   // (4,12,12)
    const float* mw    = (const float*)d_in[4];   // (4,)
    float* out = (float*)d_out;                   // (64,512,10)

    static bool attr_set = false;
    if (!attr_set) {
        cudaFuncSetAttribute(proj_kernel,
                             cudaFuncAttributeMaxDynamicSharedMemorySize,
                             HIDDEN * 12 * sizeof(float));
        attr_set = true;
    }

    setup_kernel<<<1, 1024>>>(eps, means, stril, mw);
    rnn_kernel<<<BATCH, 256>>>(x);
    proj_kernel<<<(BATCH * SEQ) / 256, 256, HIDDEN * 12 * sizeof(float)>>>(out);
}

// round 15
// speedup vs baseline: 1.2865x; 1.2865x over previous
#include <cuda_runtime.h>
#include <cuda_bf16.h>
#include <cstdint>

// Problem constants
#define RANK 2
#define INPUT_SIZE 8
#define HIDDEN 1024
#define NMIX 4
#define ALPHA 0.1f
#define BASE_SCALE 500.0f
#define DDIM 12              // 2*RANK + INPUT_SIZE
#define BATCH 64
#define SEQ 512
#define SPAN_D 10            // RANK + INPUT_SIZE

#define QSCALE 131072.0f     // 2^17 fixed-point scale for int redux
#define INV_QSCALE (1.0f / 131072.0f)

// ---------------- scratch (device globals: allocation-free) ----------------
__device__ float2 g_n2[HIDDEN];             // (n0, n1) per hidden unit
__device__ float2 g_mA[HIDDEN];             // alpha*s*(m0, m1)
__device__ float  g_IA[HIDDEN * 8];         // alpha*I  [h][8]
__device__ float  g_spanT[SPAN_D * HIDDEN]; // span transposed [d][h]
__device__ float  g_gram[8 * 100];          // per-CTA Gram partials
__device__ float  g_pinvT[HIDDEN * SPAN_D]; // pinv transposed: [h][d]
__device__ float  g_hid[(size_t)BATCH * SEQ * HIDDEN]; // 128 MB hiddens

// HW tanh approximation: single MUFU op (sm_75+)
__device__ __forceinline__ float tanh_hw(float x) {
    float r;
    asm("tanh.approx.f32 %0, %1;" : "=f"(r) : "f"(x));
    return r;
}

// warp integer sum reduction: single REDUX op, result in all lanes (sm_80+)
__device__ __forceinline__ int redux_add_s32(int v) {
    int r;
    asm volatile("redux.sync.add.s32 %0, %1, 0xffffffff;" : "=r"(r) : "r"(v));
    return r;
}

// ====================== setup phase A: 8 CTAs x 128 thr ======================
__global__ void __launch_bounds__(128) setup_a_kernel(
    const float* __restrict__ eps,     // (4,1024,12)
    const float* __restrict__ means,   // (4,12)
    const float* __restrict__ stril,   // (4,12,12)
    const float* __restrict__ mw)      // (4,)
{
    __shared__ float sL[NMIX][DDIM][DDIM];
    __shared__ float sM[NMIX][DDIM];
    __shared__ float sw[NMIX];
    __shared__ float sSpanT[SPAN_D][128];   // span for this CTA's 128 h, transposed

    const int tid = threadIdx.x;
    const int h   = blockIdx.x * 128 + tid;

    // L = tril(raw,-1) + (|diag-1e-12|+1e-12) * I
    for (int i = tid; i < NMIX * DDIM * DDIM; i += 128) {
        int r = (i / DDIM) % DDIM;
        int c = i % DDIM;
        float raw = stril[i];
        float v;
        if (r > c)      v = raw;
        else if (r == c) v = fabsf(raw - 1e-12f) + 1e-12f;
        else            v = 0.f;
        sL[i / (DDIM * DDIM)][r][c] = v;
    }
    for (int i = tid; i < NMIX * DDIM; i += 128) sM[i / DDIM][i % DDIM] = means[i];
    if (tid == 0) {
        float t4[NMIX]; float s = 0.f;
        #pragma unroll
        for (int k = 0; k < NMIX; k++) { t4[k] = fmaxf(mw[k], 1e-6f); s += t4[k]; }
        #pragma unroll
        for (int k = 0; k < NMIX; k++) sw[k] = t4[k] / s;
    }
    __syncthreads();

    // mixed[h][e] = sum_k w_k * (means[k][e] + sum_{d<=e} eps[k,h,d]*L[k,e,d])
    float mix[DDIM];
    #pragma unroll
    for (int e = 0; e < DDIM; e++) mix[e] = 0.f;

    #pragma unroll
    for (int k = 0; k < NMIX; k++) {
        float wk = sw[k];
        const float4* p = (const float4*)(eps + ((size_t)k * HIDDEN + h) * DDIM);
        float4 a = p[0], b = p[1], c = p[2];
        float ep[DDIM] = {a.x,a.y,a.z,a.w, b.x,b.y,b.z,b.w, c.x,c.y,c.z,c.w};
        #pragma unroll
        for (int e = 0; e < DDIM; e++) {
            float s = sM[k][e];
            #pragma unroll
            for (int d = 0; d <= e; d++) {   // L is lower-triangular
                s = fmaf(ep[d], sL[k][e][d], s);
            }
            mix[e] = fmaf(wk, s, mix[e]);
        }
    }

    // derive per-h constants
    const float AS = ALPHA * (BASE_SCALE / (float)HIDDEN);
    float span[SPAN_D];
    span[0] = mix[0]; span[1] = mix[1];
    #pragma unroll
    for (int d = 0; d < 8; d++) span[2 + d] = mix[4 + d];

    g_n2[h] = make_float2(mix[2], mix[3]);
    g_mA[h] = make_float2(AS * mix[0], AS * mix[1]);
    #pragma unroll
    for (int d = 0; d < 8; d++) g_IA[h * 8 + d] = ALPHA * mix[4 + d];
    #pragma unroll
    for (int d = 0; d < SPAN_D; d++) {
        sSpanT[d][tid] = span[d];
        g_spanT[d * HIDDEN + h] = span[d];   // coalesced
    }
    __syncthreads();

    // per-CTA Gram partial: thread p<100 handles pair (a,b) over 128 h via float4 LDS
    if (tid < 100) {
        int a = tid / 10, b = tid % 10;
        const float4* pa = (const float4*)&sSpanT[a][0];
        const float4* pb = (const float4*)&sSpanT[b][0];
        float s0 = 0.f, s1 = 0.f, s2 = 0.f, s3 = 0.f;
        #pragma unroll 8
        for (int i = 0; i < 32; i++) {
            float4 va = pa[i], vb = pb[i];
            s0 = fmaf(va.x, vb.x, s0);
            s1 = fmaf(va.y, vb.y, s1);
            s2 = fmaf(va.z, vb.z, s2);
            s3 = fmaf(va.w, vb.w, s3);
        }
        g_gram[blockIdx.x * 100 + tid] = (s0 + s1) + (s2 + s3);
    }
}

// ====================== setup phase B: 1 CTA, Gram sum + fp32 GJ + pinv ======
__global__ void __launch_bounds__(1024) setup_b_kernel()
{
    __shared__ float sA[100];          // Gram / GJ workspace (fp32; kappa(G)~2)
    __shared__ float sB[100];          // GJ inverse accumulator

    const int tid = threadIdx.x;

    if (tid < 100) {
        float s = 0.f;
        #pragma unroll
        for (int c = 0; c < 8; c++) s += g_gram[c * 100 + tid];
        sA[tid] = s;
        sB[tid] = ((tid / 10) == (tid % 10)) ? 1.f : 0.f;
    }

    // parallel Gauss-Jordan (SPD, no pivoting), 100 threads, fp32
    const int gi = tid / 10, gj = tid % 10;
    #pragma unroll 1
    for (int k = 0; k < SPAN_D; k++) {
        __syncthreads();
        float piv = 1.f, akj = 0.f, bkj = 0.f, f = 0.f, aij = 0.f, bij = 0.f;
        if (tid < 100) {
            piv = sA[k * 10 + k];
            akj = sA[k * 10 + gj];
            bkj = sB[k * 10 + gj];
            f   = sA[gi * 10 + k];
            aij = sA[tid];
            bij = sB[tid];
        }
        __syncthreads();
        if (tid < 100) {
            float pin = __frcp_rn(piv);
            if (gi == k) {
                sA[tid] = akj * pin;
                sB[tid] = bkj * pin;
            } else {
                float fp = f * pin;
                sA[tid] = fmaf(-fp, akj, aij);
                sB[tid] = fmaf(-fp, bkj, bij);
            }
        }
    }
    __syncthreads();

    // pinv[d][h] = sum_j Ginv[d][j] * span[h][j]; one thread per h
    const int h = tid;
    float span[SPAN_D];
    #pragma unroll
    for (int d = 0; d < SPAN_D; d++) span[d] = g_spanT[d * HIDDEN + h];
    #pragma unroll
    for (int d = 0; d < SPAN_D; d++) {
        float s = 0.f;
        #pragma unroll
        for (int j = 0; j < SPAN_D; j++) s = fmaf(sB[d * 10 + j], span[j], s);
        g_pinvT[h * SPAN_D + d] = s;
    }
}

// ============================ RNN kernel ============================
// One CTA per batch. 256 threads, each owns 4 consecutive hidden units.
// Block reduction: fixed-point int REDUX (warp) + LDS.128/IADD tree (block).
__global__ void __launch_bounds__(256, 1) rnn_kernel(const float* __restrict__ x)
{
    __shared__ float sx[SEQ * INPUT_SIZE];    // 16 KB: x[b] staged
    __shared__ int4  sred[2][4];              // ping-pong: 8 x int2(S0,S1) as 4 x int4

    const int tid  = threadIdx.x;
    const int lane = tid & 31;
    const int wid  = tid >> 5;
    const int b    = blockIdx.x;

    // stage x[b] into smem (coalesced float4)
    #pragma unroll
    for (int i = 0; i < (SEQ * INPUT_SIZE / 4) / 256; i++)
        ((float4*)sx)[i * 256 + tid] =
            ((const float4*)(x + (size_t)b * SEQ * INPUT_SIZE))[i * 256 + tid];

    // per-thread constants for h = 4*tid .. 4*tid+3
    // n scaled by 2^17 (fixed-point), m scaled by 2^-17 (decode folded in)
    float n0[4], n1[4], m0[4], m1[4], IA[4][8];
    #pragma unroll
    for (int i = 0; i < 4; i++) {
        int hh = 4 * tid + i;
        float2 t = g_n2[hh]; n0[i] = t.x * QSCALE; n1[i] = t.y * QSCALE;
        t = g_mA[hh];        m0[i] = t.x * INV_QSCALE; m1[i] = t.y * INV_QSCALE;
        float4 a4 = ((const float4*)g_IA)[hh * 2 + 0];
        float4 b4 = ((const float4*)g_IA)[hh * 2 + 1];
        IA[i][0]=a4.x; IA[i][1]=a4.y; IA[i][2]=a4.z; IA[i][3]=a4.w;
        IA[i][4]=b4.x; IA[i][5]=b4.y; IA[i][6]=b4.z; IA[i][7]=b4.w;
    }

    float h[4] = {0.f, 0.f, 0.f, 0.f};
    float* hout = g_hid + ((size_t)b << 19) + 4 * tid;   // [b][t][h]
    __syncthreads();

    int par = 0;
    #pragma unroll 1
    for (int t = 0; t < SEQ; t++) {
        // tanh via single MUFU op
        float th[4];
        #pragma unroll
        for (int i = 0; i < 4; i++) th[i] = tanh_hw(h[i]);

        // per-thread 4-way product tree (pre-scaled by 2^17)
        float p0 = fmaf(th[0], n0[0], th[1] * n0[1]) + fmaf(th[2], n0[2], th[3] * n0[3]);
        float p1 = fmaf(th[0], n1[0], th[1] * n1[1]) + fmaf(th[2], n1[2], th[3] * n1[3]);

        // fixed-point warp reduction: F2I + single REDUX op (replaces 6-shfl chain)
        int i0 = __float2int_rn(p0);
        int i1 = __float2int_rn(p1);
        int r0 = redux_add_s32(i0);
        int r1 = redux_add_s32(i1);
        if (lane == 0) ((int2*)&sred[par][0])[wid] = make_int2(r0, r1);

        // x_t @ (alpha*I)^T  — independent of the reduction, overlaps redux/bar
        float4 xa = ((const float4*)sx)[t * 2 + 0];
        float4 xb = ((const float4*)sx)[t * 2 + 1];
        float xi[4];
        #pragma unroll
        for (int i = 0; i < 4; i++) {
            xi[i] = xa.x*IA[i][0] + xa.y*IA[i][1] + xa.z*IA[i][2] + xa.w*IA[i][3]
                  + xb.x*IA[i][4] + xb.y*IA[i][5] + xb.z*IA[i][6] + xb.w*IA[i][7];
        }

        __syncthreads();
        // stage-2: 4 broadcast LDS.128 (int4) + depth-3 IADD tree, then I2F
        int4 r0v = sred[par][0];
        int4 r1v = sred[par][1];
        int4 r2v = sred[par][2];
        int4 r3v = sred[par][3];
        int s0 = ((r0v.x + r0v.z) + (r1v.x + r1v.z)) + ((r2v.x + r2v.z) + (r3v.x + r3v.z));
        int s1 = ((r0v.y + r0v.w) + (r1v.y + r1v.w)) + ((r2v.y + r2v.w) + (r3v.y + r3v.w));
        float q0 = (float)s0;   // decode 2^-17 folded into m0/m1
        float q1 = (float)s1;

        // h_new = 0.9h + q0*mA0 + q1*mA1 + xi  (scales prefolded)
        #pragma unroll
        for (int i = 0; i < 4; i++)
            h[i] = fmaf(0.9f, h[i], fmaf(q0, m0[i], fmaf(q1, m1[i], xi[i])));

        *(float4*)(hout + ((size_t)t << 10)) = make_float4(h[0], h[1], h[2], h[3]);
        par ^= 1;
    }
}

// ============================ projection kernel ============================
// out[b,t,d] = sum_h pinv[d][h] * hid[b,t,h]; thread per (b,t).
__global__ void __launch_bounds__(256) proj_kernel(float* __restrict__ out)
{
    extern __shared__ float spv[];   // [1024][12] padded pinv rows, 48 KB
    const int tid = threadIdx.x;
    for (int i = tid; i < HIDDEN * 12; i += 256) {
        int hh = i / 12, d = i % 12;
        spv[i] = (d < SPAN_D) ? g_pinvT[hh * SPAN_D + d] : 0.f;
    }
    __syncthreads();

    const int bt = blockIdx.x * 256 + tid;          // 0..32767
    const float4* hp = (const float4*)(g_hid + (size_t)bt * HIDDEN);

    float acc[SPAN_D];
    #pragma unroll
    for (int d = 0; d < SPAN_D; d++) acc[d] = 0.f;

    #pragma unroll 4
    for (int j = 0; j < HIDDEN / 4; j++) {
        float4 hv = hp[j];
        const float* base = &spv[(j * 4) * 12];
        {
            const float4* pv = (const float4*)(base + 0);
            float4 a = pv[0], bq = pv[1], c = pv[2];
            acc[0] += hv.x*a.x;  acc[1] += hv.x*a.y;  acc[2] += hv.x*a.z;  acc[3] += hv.x*a.w;
            acc[4] += hv.x*bq.x; acc[5] += hv.x*bq.y; acc[6] += hv.x*bq.z; acc[7] += hv.x*bq.w;
            acc[8] += hv.x*c.x;  acc[9] += hv.x*c.y;
        }
        {
            const float4* pv = (const float4*)(base + 12);
            float4 a = pv[0], bq = pv[1], c = pv[2];
            acc[0] += hv.y*a.x;  acc[1] += hv.y*a.y;  acc[2] += hv.y*a.z;  acc[3] += hv.y*a.w;
            acc[4] += hv.y*bq.x; acc[5] += hv.y*bq.y; acc[6] += hv.y*bq.z; acc[7] += hv.y*bq.w;
            acc[8] += hv.y*c.x;  acc[9] += hv.y*c.y;
        }
        {
            const float4* pv = (const float4*)(base + 24);
            float4 a = pv[0], bq = pv[1], c = pv[2];
            acc[0] += hv.z*a.x;  acc[1] += hv.z*a.y;  acc[2] += hv.z*a.z;  acc[3] += hv.z*a.w;
            acc[4] += hv.z*bq.x; acc[5] += hv.z*bq.y; acc[6] += hv.z*bq.z; acc[7] += hv.z*bq.w;
            acc[8] += hv.z*c.x;  acc[9] += hv.z*c.y;
        }
        {
            const float4* pv = (const float4*)(base + 36);
            float4 a = pv[0], bq = pv[1], c = pv[2];
            acc[0] += hv.w*a.x;  acc[1] += hv.w*a.y;  acc[2] += hv.w*a.z;  acc[3] += hv.w*a.w;
            acc[4] += hv.w*bq.x; acc[5] += hv.w*bq.y; acc[6] += hv.w*bq.z; acc[7] += hv.w*bq.w;
            acc[8] += hv.w*c.x;  acc[9] += hv.w*c.y;
        }
    }

    float* op = out + (size_t)bt * SPAN_D;
    #pragma unroll
    for (int d = 0; d < SPAN_D; d++) op[d] = acc[d];
}

// ============================ launcher ============================
extern "C" void kernel_launch(void* const* d_in, const int* in_sizes, int n_in,
                              void* d_out, int out_size)
{
    const float* x     = (const float*)d_in[0];   // (64,512,8)
    const float* eps   = (const float*)d_in[1];   // (4,1024,12)
    const float* means = (const float*)d_in[2];   // (4,12)
    const float* stril = (const float*)d_in[3];   // (4,12,12)
    const float* mw    = (const float*)d_in[4];   // (4,)
    float* out = (float*)d_out;                   // (64,512,10)

    static bool attr_set = false;
    if (!attr_set) {
        cudaFuncSetAttribute(proj_kernel,
                             cudaFuncAttributeMaxDynamicSharedMemorySize,
                             HIDDEN * 12 * sizeof(float));
        attr_set = true;
    }

    setup_a_kernel<<<8, 128>>>(eps, means, stril, mw);
    setup_b_kernel<<<1, 1024>>>();
    rnn_kernel<<<BATCH, 256>>>(x);
    proj_kernel<<<(BATCH * SEQ) / 256, 256, HIDDEN * 12 * sizeof(float)>>>(out);
}